// round 10
// baseline (speedup 1.0000x reference)
#include <cuda_runtime.h>

#define BB    2
#define HH    48
#define WW    48
#define CC    256
#define NHEAD 8
#define HD    32
#define LL    (HH*WW)      /* 2304 */
#define MTOT  (BB*LL)      /* 4608 */

// ---------------- scratch (device globals; no allocs allowed) ----------------
__device__ float g_q   [BB*NHEAD*LL*HD];
__device__ float g_k   [BB*NHEAD*LL*HD];
__device__ float g_vh  [BB*NHEAD*LL*HD];
__device__ float g_vn  [BB*LL*CC];
__device__ float g_lepe[BB*LL*CC];
__device__ float g_attn[BB*LL*CC];

// ---------------- helpers ------------------------------------------------------
__device__ __forceinline__ void mma_tf32(float c[4], const unsigned a[4],
                                         unsigned b0, unsigned b1) {
    asm("mma.sync.aligned.m16n8k8.row.col.f32.tf32.tf32.f32 "
        "{%0,%1,%2,%3}, {%4,%5,%6,%7}, {%8,%9}, {%0,%1,%2,%3};"
        : "+f"(c[0]), "+f"(c[1]), "+f"(c[2]), "+f"(c[3])
        : "r"(a[0]), "r"(a[1]), "r"(a[2]), "r"(a[3]), "r"(b0), "r"(b1));
}
#define TF32_HI_MASK 0xFFFFE000u
__device__ __forceinline__ void hilo(float v, unsigned& hi, unsigned& lo) {
    unsigned u = __float_as_uint(v) & TF32_HI_MASK;
    hi = u;
    lo = __float_as_uint(v - __uint_as_float(u));
}
__device__ __forceinline__ unsigned smem_u32(const void* p) {
    return (unsigned)__cvta_generic_to_shared(p);
}
__device__ __forceinline__ void cp16(unsigned dst, const void* src) {
    asm volatile("cp.async.cg.shared.global [%0], [%1], 16;" :: "r"(dst), "l"(src));
}
#define CP_COMMIT() asm volatile("cp.async.commit_group;")
#define CP_WAIT0()  asm volatile("cp.async.wait_group 0;" ::: "memory")

// ---------------- tf32 MMA GEMM: 32x128 tiles, K=256, BK=32 --------------------
#define ASTR 36
#define BSTR 132

__global__ __launch_bounds__(256) void qkv_mma(
    const float* __restrict__ x,
    const float* __restrict__ wq, const float* __restrict__ bq,
    const float* __restrict__ wk, const float* __restrict__ bk,
    const float* __restrict__ wv, const float* __restrict__ bv,
    const float* __restrict__ sinv, const float* __restrict__ cosv)
{
    const int z = blockIdx.z;
    const float* Wm   = (z == 0) ? wq : (z == 1) ? wk : wv;
    const float* bias = (z == 0) ? bq : (z == 1) ? bk : bv;

    __shared__ __align__(16) float As[32][ASTR];
    __shared__ __align__(16) float Bs[32][BSTR];

    const int t = threadIdx.x, lane = t & 31, warp = t >> 5;
    const int qr = lane >> 2, qq = lane & 3;
    const int wm = warp >> 2, wn = warp & 3;
    const int m0 = blockIdx.y * 32;
    const int n0 = blockIdx.x * 128;

    const int ar = t >> 3, ac = (t & 7) * 4;
    const int bkr = warp, bnc = lane * 4;

    float acc[4][4];
    #pragma unroll
    for (int j = 0; j < 4; j++)
        #pragma unroll
        for (int r = 0; r < 4; r++) acc[j][r] = 0.f;

    float4 aA, b4[4];
    aA = *(const float4*)&x[(m0 + ar)*CC + ac];
    #pragma unroll
    for (int u = 0; u < 4; u++)
        b4[u] = *(const float4*)&Wm[(bkr + u*8)*CC + n0 + bnc];

    for (int it = 0; it < 8; it++) {
        if (it) __syncthreads();
        *(float4*)&As[ar][ac] = aA;
        #pragma unroll
        for (int u = 0; u < 4; u++)
            *(float4*)&Bs[bkr + u*8][bnc] = b4[u];
        __syncthreads();
        if (it < 7) {
            int k0 = (it + 1) * 32;
            aA = *(const float4*)&x[(m0 + ar)*CC + k0 + ac];
            #pragma unroll
            for (int u = 0; u < 4; u++)
                b4[u] = *(const float4*)&Wm[(k0 + bkr + u*8)*CC + n0 + bnc];
        }
        #pragma unroll
        for (int kb = 0; kb < 4; kb++) {
            unsigned ahi[4], alo[4];
            int arow = wm*16 + qr;
            float a0 = As[arow    ][kb*8 + qq];
            float a1 = As[arow + 8][kb*8 + qq];
            float a2 = As[arow    ][kb*8 + qq + 4];
            float a3 = As[arow + 8][kb*8 + qq + 4];
            hilo(a0, ahi[0], alo[0]); hilo(a1, ahi[1], alo[1]);
            hilo(a2, ahi[2], alo[2]); hilo(a3, ahi[3], alo[3]);
            #pragma unroll
            for (int nf = 0; nf < 4; nf++) {
                int bcol = wn*32 + nf*8 + qr;
                float b0 = Bs[kb*8 + qq    ][bcol];
                float b1 = Bs[kb*8 + qq + 4][bcol];
                unsigned bh0, bl0, bh1, bl1;
                hilo(b0, bh0, bl0); hilo(b1, bh1, bl1);
                mma_tf32(acc[nf], ahi, bh0, bh1);
                mma_tf32(acc[nf], alo, bh0, bh1);
                mma_tf32(acc[nf], ahi, bl0, bl1);
            }
        }
    }

    const float scaling = 0.17677669529663687f;
    #pragma unroll
    for (int nf = 0; nf < 4; nf++) {
        int cbase = n0 + wn*32 + nf*8 + 2*qq;
        int n = cbase >> 5, d = cbase & 31;
        #pragma unroll
        for (int rr = 0; rr < 2; rr++) {
            int m = m0 + wm*16 + qr + rr*8;
            int bi = m / LL, l = m - bi*LL;
            float e = acc[nf][rr*2 + 0] + __ldg(&bias[cbase]);
            float o = acc[nf][rr*2 + 1] + __ldg(&bias[cbase + 1]);
            if (z == 1) { e *= scaling; o *= scaling; }
            if (z != 2) {
                float2 sv = *(const float2*)&sinv[l*HD + d];
                float2 cv = *(const float2*)&cosv[l*HD + d];
                float e2 = e*cv.x - o*sv.x;
                float o2 = o*cv.y + e*sv.y;
                e = e2; o = o2;
            }
            size_t idx = ((size_t)(bi*NHEAD + n)*LL + l)*HD + d;
            if (z == 0)      *(float2*)&g_q[idx] = make_float2(e, o);
            else if (z == 1) *(float2*)&g_k[idx] = make_float2(e, o);
            else {
                *(float2*)&g_vh[idx] = make_float2(e, o);
                *(float2*)&g_vn[((size_t)(bi*LL + l))*CC + cbase] =
                    make_float2(e, o);
            }
        }
    }
}

__global__ __launch_bounds__(256) void out_mma(const float* __restrict__ wo,
                                               const float* __restrict__ bo,
                                               float* __restrict__ out)
{
    __shared__ __align__(16) float As[32][ASTR];
    __shared__ __align__(16) float Bs[32][BSTR];

    const int t = threadIdx.x, lane = t & 31, warp = t >> 5;
    const int qr = lane >> 2, qq = lane & 3;
    const int wm = warp >> 2, wn = warp & 3;
    const int m0 = blockIdx.y * 32;
    const int n0 = blockIdx.x * 128;

    const int ar = t >> 3, ac = (t & 7) * 4;
    const int bkr = warp, bnc = lane * 4;

    float acc[4][4];
    #pragma unroll
    for (int j = 0; j < 4; j++)
        #pragma unroll
        for (int r = 0; r < 4; r++) acc[j][r] = 0.f;

    float4 aA, b4[4];
    {
        float4 u1 = *(const float4*)&g_attn[(m0 + ar)*CC + ac];
        float4 u2 = *(const float4*)&g_lepe[(m0 + ar)*CC + ac];
        aA = make_float4(u1.x+u2.x, u1.y+u2.y, u1.z+u2.z, u1.w+u2.w);
    }
    #pragma unroll
    for (int u = 0; u < 4; u++)
        b4[u] = *(const float4*)&wo[(bkr + u*8)*CC + n0 + bnc];

    for (int it = 0; it < 8; it++) {
        if (it) __syncthreads();
        *(float4*)&As[ar][ac] = aA;
        #pragma unroll
        for (int u = 0; u < 4; u++)
            *(float4*)&Bs[bkr + u*8][bnc] = b4[u];
        __syncthreads();
        if (it < 7) {
            int k0 = (it + 1) * 32;
            float4 u1 = *(const float4*)&g_attn[(m0 + ar)*CC + k0 + ac];
            float4 u2 = *(const float4*)&g_lepe[(m0 + ar)*CC + k0 + ac];
            aA = make_float4(u1.x+u2.x, u1.y+u2.y, u1.z+u2.z, u1.w+u2.w);
            #pragma unroll
            for (int u = 0; u < 4; u++)
                b4[u] = *(const float4*)&wo[(k0 + bkr + u*8)*CC + n0 + bnc];
        }
        #pragma unroll
        for (int kb = 0; kb < 4; kb++) {
            unsigned ahi[4], alo[4];
            int arow = wm*16 + qr;
            float a0 = As[arow    ][kb*8 + qq];
            float a1 = As[arow + 8][kb*8 + qq];
            float a2 = As[arow    ][kb*8 + qq + 4];
            float a3 = As[arow + 8][kb*8 + qq + 4];
            hilo(a0, ahi[0], alo[0]); hilo(a1, ahi[1], alo[1]);
            hilo(a2, ahi[2], alo[2]); hilo(a3, ahi[3], alo[3]);
            #pragma unroll
            for (int nf = 0; nf < 4; nf++) {
                int bcol = wn*32 + nf*8 + qr;
                float b0 = Bs[kb*8 + qq    ][bcol];
                float b1 = Bs[kb*8 + qq + 4][bcol];
                unsigned bh0, bl0, bh1, bl1;
                hilo(b0, bh0, bl0); hilo(b1, bh1, bl1);
                mma_tf32(acc[nf], ahi, bh0, bh1);
                mma_tf32(acc[nf], alo, bh0, bh1);
                mma_tf32(acc[nf], ahi, bl0, bl1);
            }
        }
    }

    #pragma unroll
    for (int nf = 0; nf < 4; nf++) {
        int cbase = n0 + wn*32 + nf*8 + 2*qq;
        float bx = __ldg(&bo[cbase]), by = __ldg(&bo[cbase + 1]);
        #pragma unroll
        for (int rr = 0; rr < 2; rr++) {
            int m = m0 + wm*16 + qr + rr*8;
            *(float2*)&out[(size_t)m*CC + cbase] =
                make_float2(acc[nf][rr*2] + bx, acc[nf][rr*2 + 1] + by);
        }
    }
}

// ---------------- 5x5 depthwise conv (LEPE), smem-tiled ------------------------
__global__ __launch_bounds__(256) void lepe_tiled(const float* __restrict__ wdw,
                                                  const float* __restrict__ bdw)
{
    __shared__ float patch[12*12*64];

    const int t  = threadIdx.x;
    const int tx = blockIdx.x % 6, ty = blockIdx.x / 6;
    const int cg = blockIdx.y;
    const int bi = blockIdx.z;
    const int h0 = ty*8, w0 = tx*8;
    const int c0 = cg*64;

    #pragma unroll
    for (int i = 0; i < 9; i++) {
        int fidx = t + i*256;
        int c4  = (fidx & 15) * 4;
        int pix = fidx >> 4;
        int py = pix / 12, px = pix % 12;
        int hy = h0 + py - 2, wx = w0 + px - 2;
        float4 v = make_float4(0.f, 0.f, 0.f, 0.f);
        if (hy >= 0 && hy < HH && wx >= 0 && wx < WW)
            v = *(const float4*)&g_vn[((size_t)(bi*LL + hy*WW + wx))*CC + c0 + c4];
        *(float4*)&patch[(py*12 + px)*64 + c4] = v;
    }

    const int c  = t & 63;
    const int pg = t >> 6;
    float wr[25];
    #pragma unroll
    for (int i = 0; i < 25; i++) wr[i] = __ldg(&wdw[i*CC + c0 + c]);
    const float bias = __ldg(&bdw[c0 + c]);

    __syncthreads();

    #pragma unroll
    for (int j = 0; j < 16; j++) {
        int pid = pg*16 + j;
        int py = pid >> 3, px = pid & 7;
        float acc = bias;
        #pragma unroll
        for (int dy = 0; dy < 5; dy++)
            #pragma unroll
            for (int dx = 0; dx < 5; dx++)
                acc += patch[((py+dy)*12 + (px+dx))*64 + c] * wr[dy*5+dx];
        g_lepe[((size_t)(bi*LL + (h0+py)*WW + (w0+px)))*CC + c0 + c] = acc;
    }
}

// ---------------- flash attention: 256-row CTA, 32 rows/warp -------------------
#define KSTR 36
#define PSTR 68
#define KVSZ (64*KSTR)
#define ATTN_SMEM ((4*KVSZ + 256*PSTR) * 4)

__global__ __launch_bounds__(256, 1) void attn_mma(const float* __restrict__ mask)
{
    extern __shared__ __align__(16) float smem[];
    float* Kst[2] = { smem,          smem + KVSZ   };
    float* Vst[2] = { smem + 2*KVSZ, smem + 3*KVSZ };
    float (*Psh)[PSTR] = (float(*)[PSTR])(smem + 4*KVSZ);

    const int bi = blockIdx.x;
    const int l0 = blockIdx.y * 256;
    const int n  = blockIdx.z;
    const int t = threadIdx.x, lane = t & 31, warp = t >> 5;
    const int qr = lane >> 2, qq = lane & 3;

    const int bn = bi*NHEAD + n;
    const float* qg = g_q  + (size_t)bn*LL*HD;
    const float* kg = g_k  + (size_t)bn*LL*HD;
    const float* vg = g_vh + (size_t)bn*LL*HD;

    const int row0 = l0 + warp*32 + qr;     // rows row0 + {0,8,16,24}
    const float* mrow[4];
    #pragma unroll
    for (int g = 0; g < 4; g++)
        mrow[g] = mask + (size_t)n*LL*LL + (size_t)(row0 + g*8)*LL;

    // cp.async slots
    const int lr = t >> 3, lc = (t & 7) * 4;
    unsigned kd0[2], kd1[2], vd0[2], vd1[2];
    #pragma unroll
    for (int ss = 0; ss < 2; ss++) {
        kd0[ss] = smem_u32(&Kst[ss][lr*KSTR + lc]);
        kd1[ss] = smem_u32(&Kst[ss][(lr + 32)*KSTR + lc]);
        vd0[ss] = smem_u32(&Vst[ss][lr*KSTR + lc]);
        vd1[ss] = smem_u32(&Vst[ss][(lr + 32)*KSTR + lc]);
    }
    cp16(kd0[0], &kg[(size_t)lr*HD + lc]);
    cp16(kd1[0], &kg[(size_t)(lr + 32)*HD + lc]);
    cp16(vd0[0], &vg[(size_t)lr*HD + lc]);
    cp16(vd1[0], &vg[(size_t)(lr + 32)*HD + lc]);
    CP_COMMIT();

    // Q fragments: 2 m-frags x 4 k-chunks
    unsigned qA[2][4][4];
    #pragma unroll
    for (int mf = 0; mf < 2; mf++) {
        int r = row0 + mf*16;
        #pragma unroll
        for (int k = 0; k < 4; k++) {
            qA[mf][k][0] = __float_as_uint(qg[(r    )*HD + k*8 + qq    ]);
            qA[mf][k][1] = __float_as_uint(qg[(r + 8)*HD + k*8 + qq    ]);
            qA[mf][k][2] = __float_as_uint(qg[(r    )*HD + k*8 + qq + 4]);
            qA[mf][k][3] = __float_as_uint(qg[(r + 8)*HD + k*8 + qq + 4]);
        }
    }

    // s starts as mask tile 0
    float s[2][8][4];
    #pragma unroll
    for (int mf = 0; mf < 2; mf++)
        #pragma unroll
        for (int jn = 0; jn < 8; jn++) {
            float2 a = __ldg((const float2*)&mrow[mf*2    ][jn*8 + 2*qq]);
            float2 b = __ldg((const float2*)&mrow[mf*2 + 1][jn*8 + 2*qq]);
            s[mf][jn][0] = a.x; s[mf][jn][1] = a.y;
            s[mf][jn][2] = b.x; s[mf][jn][3] = b.y;
        }

    float o[2][4][4];
    #pragma unroll
    for (int mf = 0; mf < 2; mf++)
        #pragma unroll
        for (int i = 0; i < 4; i++)
            #pragma unroll
            for (int j = 0; j < 4; j++) o[mf][i][j] = 0.f;
    float rm[4] = {-1e30f, -1e30f, -1e30f, -1e30f};
    float sum[4] = {0.f, 0.f, 0.f, 0.f};
    const int pr = warp*32 + qr;

    for (int tix = 0; tix < LL/64; tix++) {
        const int cur = tix & 1;
        const int j0 = tix * 64;
        CP_WAIT0();
        __syncthreads();
        if (tix + 1 < LL/64) {
            const float* kn = kg + (size_t)(j0 + 64)*HD;
            const float* vn = vg + (size_t)(j0 + 64)*HD;
            int nxt = cur ^ 1;
            cp16(kd0[nxt], &kn[(size_t)lr*HD + lc]);
            cp16(kd1[nxt], &kn[(size_t)(lr + 32)*HD + lc]);
            cp16(vd0[nxt], &vn[(size_t)lr*HD + lc]);
            cp16(vd1[nxt], &vn[(size_t)(lr + 0) == 0 ? (lr + 32)*HD + lc : (lr + 32)*HD + lc]);
            CP_COMMIT();
        }
        const float* Ksh = Kst[cur];
        const float* Vsh = Vst[cur];

        // ---- S = mask + Q K^T : K b-frags shared across both m-frags ----
        #pragma unroll
        for (int k = 0; k < 4; k++) {
            #pragma unroll
            for (int jn = 0; jn < 8; jn++) {
                unsigned b0 = __float_as_uint(Ksh[(jn*8 + qr)*KSTR + k*8 + qq    ]);
                unsigned b1 = __float_as_uint(Ksh[(jn*8 + qr)*KSTR + k*8 + qq + 4]);
                mma_tf32(s[0][jn], qA[0][k], b0, b1);
                mma_tf32(s[1][jn], qA[1][k], b0, b1);
            }
        }

        // ---- online softmax: 4 independent row groups ----
        float tm[4] = {-1e30f, -1e30f, -1e30f, -1e30f};
        #pragma unroll
        for (int mf = 0; mf < 2; mf++)
            #pragma unroll
            for (int jn = 0; jn < 8; jn++) {
                tm[mf*2    ] = fmaxf(tm[mf*2    ], fmaxf(s[mf][jn][0], s[mf][jn][1]));
                tm[mf*2 + 1] = fmaxf(tm[mf*2 + 1], fmaxf(s[mf][jn][2], s[mf][jn][3]));
            }
        #pragma unroll
        for (int g = 0; g < 4; g++) {
            tm[g] = fmaxf(tm[g], __shfl_xor_sync(0xffffffffu, tm[g], 1));
            tm[g] = fmaxf(tm[g], __shfl_xor_sync(0xffffffffu, tm[g], 2));
        }
        float sc[4], ts[4] = {0.f, 0.f, 0.f, 0.f};
        #pragma unroll
        for (int g = 0; g < 4; g++) {
            float nm = fmaxf(rm[g], tm[g]);
            sc[g] = __expf(rm[g] - nm);
            rm[g] = nm;
        }
        #pragma unroll
        for (int mf = 0; mf < 2; mf++)
            #pragma unroll
            for (int jn = 0; jn < 8; jn++) {
                s[mf][jn][0] = __expf(s[mf][jn][0] - rm[mf*2    ]);
                s[mf][jn][1] = __expf(s[mf][jn][1] - rm[mf*2    ]);
                s[mf][jn][2] = __expf(s[mf][jn][2] - rm[mf*2 + 1]);
                s[mf][jn][3] = __expf(s[mf][jn][3] - rm[mf*2 + 1]);
                ts[mf*2    ] += s[mf][jn][0] + s[mf][jn][1];
                ts[mf*2 + 1] += s[mf][jn][2] + s[mf][jn][3];
            }
        #pragma unroll
        for (int g = 0; g < 4; g++) {
            ts[g] += __shfl_xor_sync(0xffffffffu, ts[g], 1);
            ts[g] += __shfl_xor_sync(0xffffffffu, ts[g], 2);
            sum[g] = sum[g]*sc[g] + ts[g];
        }
        #pragma unroll
        for (int mf = 0; mf < 2; mf++)
            #pragma unroll
            for (int dn = 0; dn < 4; dn++) {
                o[mf][dn][0] *= sc[mf*2];     o[mf][dn][1] *= sc[mf*2];
                o[mf][dn][2] *= sc[mf*2 + 1]; o[mf][dn][3] *= sc[mf*2 + 1];
            }

        // ---- P -> shared (warp-local) ----
        #pragma unroll
        for (int mf = 0; mf < 2; mf++)
            #pragma unroll
            for (int jn = 0; jn < 8; jn++) {
                *(float2*)&Psh[pr + mf*16    ][jn*8 + 2*qq] =
                    make_float2(s[mf][jn][0], s[mf][jn][1]);
                *(float2*)&Psh[pr + mf*16 + 8][jn*8 + 2*qq] =
                    make_float2(s[mf][jn][2], s[mf][jn][3]);
            }
        __syncwarp();

        // ---- dead s regs: prefetch next tile's mask ----
        if (tix + 1 < LL/64) {
            const int j0n = j0 + 64;
            #pragma unroll
            for (int mf = 0; mf < 2; mf++)
                #pragma unroll
                for (int jn = 0; jn < 8; jn++) {
                    float2 a = __ldg((const float2*)&mrow[mf*2    ][j0n + jn*8 + 2*qq]);
                    float2 b = __ldg((const float2*)&mrow[mf*2 + 1][j0n + jn*8 + 2*qq]);
                    s[mf][jn][0] = a.x; s[mf][jn][1] = a.y;
                    s[mf][jn][2] = b.x; s[mf][jn][3] = b.y;
                }
        }

        // ---- O += P V : V b-frags shared across both m-frags ----
        #pragma unroll
        for (int kk = 0; kk < 8; kk++) {
            unsigned a[2][4];
            #pragma unroll
            for (int mf = 0; mf < 2; mf++) {
                a[mf][0] = __float_as_uint(Psh[pr + mf*16    ][kk*8 + qq    ]);
                a[mf][1] = __float_as_uint(Psh[pr + mf*16 + 8][kk*8 + qq    ]);
                a[mf][2] = __float_as_uint(Psh[pr + mf*16    ][kk*8 + qq + 4]);
                a[mf][3] = __float_as_uint(Psh[pr + mf*16 + 8][kk*8 + qq + 4]);
            }
            #pragma unroll
            for (int dn = 0; dn < 4; dn++) {
                unsigned b0 = __float_as_uint(Vsh[(kk*8 + qq    )*KSTR + dn*8 + qr]);
                unsigned b1 = __float_as_uint(Vsh[(kk*8 + qq + 4)*KSTR + dn*8 + qr]);
                mma_tf32(o[0][dn], a[0], b0, b1);
                mma_tf32(o[1][dn], a[1], b0, b1);
            }
        }
    }

    #pragma unroll
    for (int mf = 0; mf < 2; mf++) {
        float inv0 = 1.f / sum[mf*2], inv1 = 1.f / sum[mf*2 + 1];
        float* og0 = g_attn + ((size_t)(bi*LL + row0 + mf*16    ))*CC + n*HD;
        float* og1 = g_attn + ((size_t)(bi*LL + row0 + mf*16 + 8))*CC + n*HD;
        #pragma unroll
        for (int dn = 0; dn < 4; dn++) {
            *(float2*)&og0[dn*8 + 2*qq] =
                make_float2(o[mf][dn][0]*inv0, o[mf][dn][1]*inv0);
            *(float2*)&og1[dn*8 + 2*qq] =
                make_float2(o[mf][dn][2]*inv1, o[mf][dn][3]*inv1);
        }
    }
}

// ---------------- launch -------------------------------------------------------
extern "C" void kernel_launch(void* const* d_in, const int* in_sizes, int n_in,
                              void* d_out, int out_size)
{
    const float* x    = (const float*)d_in[0];
    const float* sinv = (const float*)d_in[1];
    const float* cosv = (const float*)d_in[2];
    const float* mask = (const float*)d_in[3];
    const float* wq   = (const float*)d_in[4];
    const float* bq   = (const float*)d_in[5];
    const float* wk   = (const float*)d_in[6];
    const float* bk   = (const float*)d_in[7];
    const float* wv   = (const float*)d_in[8];
    const float* bv   = (const float*)d_in[9];
    const float* wdw  = (const float*)d_in[10];
    const float* bdw  = (const float*)d_in[11];
    const float* wo   = (const float*)d_in[12];
    const float* bo   = (const float*)d_in[13];
    float* out = (float*)d_out;

    cudaFuncSetAttribute(attn_mma, cudaFuncAttributeMaxDynamicSharedMemorySize,
                         ATTN_SMEM);

    qkv_mma<<<dim3(CC/128, MTOT/32, 3), 256>>>(x, wq, bq, wk, bk, wv, bv,
                                               sinv, cosv);

    lepe_tiled<<<dim3(36, 4, BB), 256>>>(wdw, bdw);

    attn_mma<<<dim3(BB, LL/256, NHEAD), 256, ATTN_SMEM>>>(mask);

    out_mma<<<dim3(CC/128, MTOT/32), 256>>>(wo, bo, out);
}

// round 11
// speedup vs baseline: 1.1354x; 1.1354x over previous
#include <cuda_runtime.h>

#define BB    2
#define HH    48
#define WW    48
#define CC    256
#define NHEAD 8
#define HD    32
#define LL    (HH*WW)      /* 2304 */
#define MTOT  (BB*LL)      /* 4608 */

// ---------------- scratch (device globals; no allocs allowed) ----------------
__device__ float g_q   [BB*NHEAD*LL*HD];
__device__ float g_k   [BB*NHEAD*LL*HD];
__device__ float g_vh  [BB*NHEAD*LL*HD];
__device__ float g_vn  [BB*LL*CC];
__device__ float g_lepe[BB*LL*CC];
__device__ float g_attn[BB*LL*CC];

// ---------------- helpers ------------------------------------------------------
__device__ __forceinline__ void mma_tf32(float c[4], const unsigned a[4],
                                         unsigned b0, unsigned b1) {
    asm("mma.sync.aligned.m16n8k8.row.col.f32.tf32.tf32.f32 "
        "{%0,%1,%2,%3}, {%4,%5,%6,%7}, {%8,%9}, {%0,%1,%2,%3};"
        : "+f"(c[0]), "+f"(c[1]), "+f"(c[2]), "+f"(c[3])
        : "r"(a[0]), "r"(a[1]), "r"(a[2]), "r"(a[3]), "r"(b0), "r"(b1));
}
#define TF32_HI_MASK 0xFFFFE000u
__device__ __forceinline__ void hilo(float v, unsigned& hi, unsigned& lo) {
    unsigned u = __float_as_uint(v) & TF32_HI_MASK;
    hi = u;
    lo = __float_as_uint(v - __uint_as_float(u));
}
__device__ __forceinline__ unsigned smem_u32(const void* p) {
    return (unsigned)__cvta_generic_to_shared(p);
}
__device__ __forceinline__ void cp16(unsigned dst, const void* src) {
    asm volatile("cp.async.cg.shared.global [%0], [%1], 16;" :: "r"(dst), "l"(src));
}
#define CP_COMMIT() asm volatile("cp.async.commit_group;")
#define CP_WAIT0()  asm volatile("cp.async.wait_group 0;" ::: "memory")

// ---------------- tf32 MMA GEMM: 32x128 tiles, K=256, BK=32 --------------------
// A split hi/lo (exact), B raw tf32: 2 MMAs per product, err ~ tf32 eps on B.
#define ASTR 36
#define BSTR 132

__global__ __launch_bounds__(256) void qkv_mma(
    const float* __restrict__ x,
    const float* __restrict__ wq, const float* __restrict__ bq,
    const float* __restrict__ wk, const float* __restrict__ bk,
    const float* __restrict__ wv, const float* __restrict__ bv,
    const float* __restrict__ sinv, const float* __restrict__ cosv)
{
    const int z = blockIdx.z;
    const float* Wm   = (z == 0) ? wq : (z == 1) ? wk : wv;
    const float* bias = (z == 0) ? bq : (z == 1) ? bk : bv;

    __shared__ __align__(16) float As[32][ASTR];
    __shared__ __align__(16) float Bs[32][BSTR];

    const int t = threadIdx.x, lane = t & 31, warp = t >> 5;
    const int qr = lane >> 2, qq = lane & 3;
    const int wm = warp >> 2, wn = warp & 3;
    const int m0 = blockIdx.y * 32;
    const int n0 = blockIdx.x * 128;

    const int ar = t >> 3, ac = (t & 7) * 4;
    const int bkr = warp, bnc = lane * 4;

    float acc[4][4];
    #pragma unroll
    for (int j = 0; j < 4; j++)
        #pragma unroll
        for (int r = 0; r < 4; r++) acc[j][r] = 0.f;

    float4 aA, b4[4];
    aA = *(const float4*)&x[(m0 + ar)*CC + ac];
    #pragma unroll
    for (int u = 0; u < 4; u++)
        b4[u] = *(const float4*)&Wm[(bkr + u*8)*CC + n0 + bnc];

    for (int it = 0; it < 8; it++) {
        if (it) __syncthreads();
        *(float4*)&As[ar][ac] = aA;
        #pragma unroll
        for (int u = 0; u < 4; u++)
            *(float4*)&Bs[bkr + u*8][bnc] = b4[u];
        __syncthreads();
        if (it < 7) {
            int k0 = (it + 1) * 32;
            aA = *(const float4*)&x[(m0 + ar)*CC + k0 + ac];
            #pragma unroll
            for (int u = 0; u < 4; u++)
                b4[u] = *(const float4*)&Wm[(k0 + bkr + u*8)*CC + n0 + bnc];
        }
        #pragma unroll
        for (int kb = 0; kb < 4; kb++) {
            unsigned ahi[4], alo[4];
            int arow = wm*16 + qr;
            float a0 = As[arow    ][kb*8 + qq];
            float a1 = As[arow + 8][kb*8 + qq];
            float a2 = As[arow    ][kb*8 + qq + 4];
            float a3 = As[arow + 8][kb*8 + qq + 4];
            hilo(a0, ahi[0], alo[0]); hilo(a1, ahi[1], alo[1]);
            hilo(a2, ahi[2], alo[2]); hilo(a3, ahi[3], alo[3]);
            #pragma unroll
            for (int nf = 0; nf < 4; nf++) {
                int bcol = wn*32 + nf*8 + qr;
                unsigned b0 = __float_as_uint(Bs[kb*8 + qq    ][bcol]);
                unsigned b1 = __float_as_uint(Bs[kb*8 + qq + 4][bcol]);
                mma_tf32(acc[nf], ahi, b0, b1);
                mma_tf32(acc[nf], alo, b0, b1);
            }
        }
    }

    const float scaling = 0.17677669529663687f;
    #pragma unroll
    for (int nf = 0; nf < 4; nf++) {
        int cbase = n0 + wn*32 + nf*8 + 2*qq;
        int n = cbase >> 5, d = cbase & 31;
        #pragma unroll
        for (int rr = 0; rr < 2; rr++) {
            int m = m0 + wm*16 + qr + rr*8;
            int bi = m / LL, l = m - bi*LL;
            float e = acc[nf][rr*2 + 0] + __ldg(&bias[cbase]);
            float o = acc[nf][rr*2 + 1] + __ldg(&bias[cbase + 1]);
            if (z == 1) { e *= scaling; o *= scaling; }
            if (z != 2) {
                float2 sv = *(const float2*)&sinv[l*HD + d];
                float2 cv = *(const float2*)&cosv[l*HD + d];
                float e2 = e*cv.x - o*sv.x;
                float o2 = o*cv.y + e*sv.y;
                e = e2; o = o2;
            }
            size_t idx = ((size_t)(bi*NHEAD + n)*LL + l)*HD + d;
            if (z == 0)      *(float2*)&g_q[idx] = make_float2(e, o);
            else if (z == 1) *(float2*)&g_k[idx] = make_float2(e, o);
            else {
                *(float2*)&g_vh[idx] = make_float2(e, o);
                *(float2*)&g_vn[((size_t)(bi*LL + l))*CC + cbase] =
                    make_float2(e, o);
            }
        }
    }
}

__global__ __launch_bounds__(256) void out_mma(const float* __restrict__ wo,
                                               const float* __restrict__ bo,
                                               float* __restrict__ out)
{
    __shared__ __align__(16) float As[32][ASTR];
    __shared__ __align__(16) float Bs[32][BSTR];

    const int t = threadIdx.x, lane = t & 31, warp = t >> 5;
    const int qr = lane >> 2, qq = lane & 3;
    const int wm = warp >> 2, wn = warp & 3;
    const int m0 = blockIdx.y * 32;
    const int n0 = blockIdx.x * 128;

    const int ar = t >> 3, ac = (t & 7) * 4;
    const int bkr = warp, bnc = lane * 4;

    float acc[4][4];
    #pragma unroll
    for (int j = 0; j < 4; j++)
        #pragma unroll
        for (int r = 0; r < 4; r++) acc[j][r] = 0.f;

    float4 aA, b4[4];
    {
        float4 u1 = *(const float4*)&g_attn[(m0 + ar)*CC + ac];
        float4 u2 = *(const float4*)&g_lepe[(m0 + ar)*CC + ac];
        aA = make_float4(u1.x+u2.x, u1.y+u2.y, u1.z+u2.z, u1.w+u2.w);
    }
    #pragma unroll
    for (int u = 0; u < 4; u++)
        b4[u] = *(const float4*)&wo[(bkr + u*8)*CC + n0 + bnc];

    for (int it = 0; it < 8; it++) {
        if (it) __syncthreads();
        *(float4*)&As[ar][ac] = aA;
        #pragma unroll
        for (int u = 0; u < 4; u++)
            *(float4*)&Bs[bkr + u*8][bnc] = b4[u];
        __syncthreads();
        if (it < 7) {
            int k0 = (it + 1) * 32;
            float4 u1 = *(const float4*)&g_attn[(m0 + ar)*CC + k0 + ac];
            float4 u2 = *(const float4*)&g_lepe[(m0 + ar)*CC + k0 + ac];
            aA = make_float4(u1.x+u2.x, u1.y+u2.y, u1.z+u2.z, u1.w+u2.w);
            #pragma unroll
            for (int u = 0; u < 4; u++)
                b4[u] = *(const float4*)&wo[(k0 + bkr + u*8)*CC + n0 + bnc];
        }
        #pragma unroll
        for (int kb = 0; kb < 4; kb++) {
            unsigned ahi[4], alo[4];
            int arow = wm*16 + qr;
            float a0 = As[arow    ][kb*8 + qq];
            float a1 = As[arow + 8][kb*8 + qq];
            float a2 = As[arow    ][kb*8 + qq + 4];
            float a3 = As[arow + 8][kb*8 + qq + 4];
            hilo(a0, ahi[0], alo[0]); hilo(a1, ahi[1], alo[1]);
            hilo(a2, ahi[2], alo[2]); hilo(a3, ahi[3], alo[3]);
            #pragma unroll
            for (int nf = 0; nf < 4; nf++) {
                int bcol = wn*32 + nf*8 + qr;
                unsigned b0 = __float_as_uint(Bs[kb*8 + qq    ][bcol]);
                unsigned b1 = __float_as_uint(Bs[kb*8 + qq + 4][bcol]);
                mma_tf32(acc[nf], ahi, b0, b1);
                mma_tf32(acc[nf], alo, b0, b1);
            }
        }
    }

    #pragma unroll
    for (int nf = 0; nf < 4; nf++) {
        int cbase = n0 + wn*32 + nf*8 + 2*qq;
        float bx = __ldg(&bo[cbase]), by = __ldg(&bo[cbase + 1]);
        #pragma unroll
        for (int rr = 0; rr < 2; rr++) {
            int m = m0 + wm*16 + qr + rr*8;
            *(float2*)&out[(size_t)m*CC + cbase] =
                make_float2(acc[nf][rr*2] + bx, acc[nf][rr*2 + 1] + by);
        }
    }
}

// ---------------- 5x5 depthwise conv (LEPE), smem-tiled ------------------------
__global__ __launch_bounds__(256) void lepe_tiled(const float* __restrict__ wdw,
                                                  const float* __restrict__ bdw)
{
    __shared__ float patch[12*12*64];

    const int t  = threadIdx.x;
    const int tx = blockIdx.x % 6, ty = blockIdx.x / 6;
    const int cg = blockIdx.y;
    const int bi = blockIdx.z;
    const int h0 = ty*8, w0 = tx*8;
    const int c0 = cg*64;

    #pragma unroll
    for (int i = 0; i < 9; i++) {
        int fidx = t + i*256;
        int c4  = (fidx & 15) * 4;
        int pix = fidx >> 4;
        int py = pix / 12, px = pix % 12;
        int hy = h0 + py - 2, wx = w0 + px - 2;
        float4 v = make_float4(0.f, 0.f, 0.f, 0.f);
        if (hy >= 0 && hy < HH && wx >= 0 && wx < WW)
            v = *(const float4*)&g_vn[((size_t)(bi*LL + hy*WW + wx))*CC + c0 + c4];
        *(float4*)&patch[(py*12 + px)*64 + c4] = v;
    }

    const int c  = t & 63;
    const int pg = t >> 6;
    float wr[25];
    #pragma unroll
    for (int i = 0; i < 25; i++) wr[i] = __ldg(&wdw[i*CC + c0 + c]);
    const float bias = __ldg(&bdw[c0 + c]);

    __syncthreads();

    #pragma unroll
    for (int j = 0; j < 16; j++) {
        int pid = pg*16 + j;
        int py = pid >> 3, px = pid & 7;
        float acc = bias;
        #pragma unroll
        for (int dy = 0; dy < 5; dy++)
            #pragma unroll
            for (int dx = 0; dx < 5; dx++)
                acc += patch[((py+dy)*12 + (px+dx))*64 + c] * wr[dy*5+dx];
        g_lepe[((size_t)(bi*LL + (h0+py)*WW + (w0+px)))*CC + c0 + c] = acc;
    }
}

// ---------------- flash attention: 128-row CTA, 4 warps, 32 rows/warp ----------
#define KSTR 36
#define PSTR 68
#define KVSZ (64*KSTR)
#define ATTN_SMEM ((4*KVSZ + 128*PSTR) * 4)

__global__ __launch_bounds__(128, 2) void attn_mma(const float* __restrict__ mask)
{
    extern __shared__ __align__(16) float smem[];
    float* Kst[2] = { smem,          smem + KVSZ   };
    float* Vst[2] = { smem + 2*KVSZ, smem + 3*KVSZ };
    float (*Psh)[PSTR] = (float(*)[PSTR])(smem + 4*KVSZ);

    const int bi = blockIdx.x;
    const int l0 = blockIdx.y * 128;
    const int n  = blockIdx.z;
    const int t = threadIdx.x, lane = t & 31, warp = t >> 5;
    const int qr = lane >> 2, qq = lane & 3;

    const int bn = bi*NHEAD + n;
    const float* qg = g_q  + (size_t)bn*LL*HD;
    const float* kg = g_k  + (size_t)bn*LL*HD;
    const float* vg = g_vh + (size_t)bn*LL*HD;

    const int row0 = l0 + warp*32 + qr;     // rows row0 + {0,8,16,24}
    const float* mrow[4];
    #pragma unroll
    for (int g = 0; g < 4; g++)
        mrow[g] = mask + (size_t)n*LL*LL + (size_t)(row0 + g*8)*LL;

    // cp.async: thread t loads K/V rows (t>>2) and (t>>2)+32, cols (t&3)*8..+7
    const int lr = t >> 2, lc = (t & 3) * 8;
    unsigned kda[2][4], vda[2][4];
    #pragma unroll
    for (int ss = 0; ss < 2; ss++) {
        kda[ss][0] = smem_u32(&Kst[ss][lr*KSTR + lc]);
        kda[ss][1] = smem_u32(&Kst[ss][lr*KSTR + lc + 4]);
        kda[ss][2] = smem_u32(&Kst[ss][(lr + 32)*KSTR + lc]);
        kda[ss][3] = smem_u32(&Kst[ss][(lr + 32)*KSTR + lc + 4]);
        vda[ss][0] = smem_u32(&Vst[ss][lr*KSTR + lc]);
        vda[ss][1] = smem_u32(&Vst[ss][lr*KSTR + lc + 4]);
        vda[ss][2] = smem_u32(&Vst[ss][(lr + 32)*KSTR + lc]);
        vda[ss][3] = smem_u32(&Vst[ss][(lr + 32)*KSTR + lc + 4]);
    }
    cp16(kda[0][0], &kg[(size_t)lr*HD + lc]);
    cp16(kda[0][1], &kg[(size_t)lr*HD + lc + 4]);
    cp16(kda[0][2], &kg[(size_t)(lr + 32)*HD + lc]);
    cp16(kda[0][3], &kg[(size_t)(lr + 32)*HD + lc + 4]);
    cp16(vda[0][0], &vg[(size_t)lr*HD + lc]);
    cp16(vda[0][1], &vg[(size_t)lr*HD + lc + 4]);
    cp16(vda[0][2], &vg[(size_t)(lr + 32)*HD + lc]);
    cp16(vda[0][3], &vg[(size_t)(lr + 32)*HD + lc + 4]);
    CP_COMMIT();

    // Q fragments: 2 m-frags x 4 k-chunks
    unsigned qA[2][4][4];
    #pragma unroll
    for (int mf = 0; mf < 2; mf++) {
        int r = row0 + mf*16;
        #pragma unroll
        for (int k = 0; k < 4; k++) {
            qA[mf][k][0] = __float_as_uint(qg[(r    )*HD + k*8 + qq    ]);
            qA[mf][k][1] = __float_as_uint(qg[(r + 8)*HD + k*8 + qq    ]);
            qA[mf][k][2] = __float_as_uint(qg[(r    )*HD + k*8 + qq + 4]);
            qA[mf][k][3] = __float_as_uint(qg[(r + 8)*HD + k*8 + qq + 4]);
        }
    }

    // s starts as mask tile 0
    float s[2][8][4];
    #pragma unroll
    for (int mf = 0; mf < 2; mf++)
        #pragma unroll
        for (int jn = 0; jn < 8; jn++) {
            float2 a = __ldg((const float2*)&mrow[mf*2    ][jn*8 + 2*qq]);
            float2 b = __ldg((const float2*)&mrow[mf*2 + 1][jn*8 + 2*qq]);
            s[mf][jn][0] = a.x; s[mf][jn][1] = a.y;
            s[mf][jn][2] = b.x; s[mf][jn][3] = b.y;
        }

    float o[2][4][4];
    #pragma unroll
    for (int mf = 0; mf < 2; mf++)
        #pragma unroll
        for (int i = 0; i < 4; i++)
            #pragma unroll
            for (int j = 0; j < 4; j++) o[mf][i][j] = 0.f;
    float rm[4] = {-1e30f, -1e30f, -1e30f, -1e30f};
    float sum[4] = {0.f, 0.f, 0.f, 0.f};
    const int pr = warp*32 + qr;

    for (int tix = 0; tix < LL/64; tix++) {
        const int cur = tix & 1;
        const int j0 = tix * 64;
        CP_WAIT0();
        __syncthreads();
        if (tix + 1 < LL/64) {
            const float* kn = kg + (size_t)(j0 + 64)*HD;
            const float* vn = vg + (size_t)(j0 + 64)*HD;
            int nxt = cur ^ 1;
            cp16(kda[nxt][0], &kn[(size_t)lr*HD + lc]);
            cp16(kda[nxt][1], &kn[(size_t)lr*HD + lc + 4]);
            cp16(kda[nxt][2], &kn[(size_t)(lr + 32)*HD + lc]);
            cp16(kda[nxt][3], &kn[(size_t)(lr + 32)*HD + lc + 4]);
            cp16(vda[nxt][0], &vn[(size_t)lr*HD + lc]);
            cp16(vda[nxt][1], &vn[(size_t)lr*HD + lc + 4]);
            cp16(vda[nxt][2], &vn[(size_t)(lr + 32)*HD + lc]);
            cp16(vda[nxt][3], &vn[(size_t)(lr + 32)*HD + lc + 4]);
            CP_COMMIT();
        }
        const float* Ksh = Kst[cur];
        const float* Vsh = Vst[cur];

        // ---- S = mask + Q K^T : K b-frags shared across both m-frags ----
        #pragma unroll
        for (int k = 0; k < 4; k++) {
            #pragma unroll
            for (int jn = 0; jn < 8; jn++) {
                unsigned b0 = __float_as_uint(Ksh[(jn*8 + qr)*KSTR + k*8 + qq    ]);
                unsigned b1 = __float_as_uint(Ksh[(jn*8 + qr)*KSTR + k*8 + qq + 4]);
                mma_tf32(s[0][jn], qA[0][k], b0, b1);
                mma_tf32(s[1][jn], qA[1][k], b0, b1);
            }
        }

        // ---- online softmax: 4 independent row groups ----
        float tm[4] = {-1e30f, -1e30f, -1e30f, -1e30f};
        #pragma unroll
        for (int mf = 0; mf < 2; mf++)
            #pragma unroll
            for (int jn = 0; jn < 8; jn++) {
                tm[mf*2    ] = fmaxf(tm[mf*2    ], fmaxf(s[mf][jn][0], s[mf][jn][1]));
                tm[mf*2 + 1] = fmaxf(tm[mf*2 + 1], fmaxf(s[mf][jn][2], s[mf][jn][3]));
            }
        #pragma unroll
        for (int g = 0; g < 4; g++) {
            tm[g] = fmaxf(tm[g], __shfl_xor_sync(0xffffffffu, tm[g], 1));
            tm[g] = fmaxf(tm[g], __shfl_xor_sync(0xffffffffu, tm[g], 2));
        }
        float sc[4], ts[4] = {0.f, 0.f, 0.f, 0.f};
        #pragma unroll
        for (int g = 0; g < 4; g++) {
            float nm = fmaxf(rm[g], tm[g]);
            sc[g] = __expf(rm[g] - nm);
            rm[g] = nm;
        }
        #pragma unroll
        for (int mf = 0; mf < 2; mf++)
            #pragma unroll
            for (int jn = 0; jn < 8; jn++) {
                s[mf][jn][0] = __expf(s[mf][jn][0] - rm[mf*2    ]);
                s[mf][jn][1] = __expf(s[mf][jn][1] - rm[mf*2    ]);
                s[mf][jn][2] = __expf(s[mf][jn][2] - rm[mf*2 + 1]);
                s[mf][jn][3] = __expf(s[mf][jn][3] - rm[mf*2 + 1]);
                ts[mf*2    ] += s[mf][jn][0] + s[mf][jn][1];
                ts[mf*2 + 1] += s[mf][jn][2] + s[mf][jn][3];
            }
        #pragma unroll
        for (int g = 0; g < 4; g++) {
            ts[g] += __shfl_xor_sync(0xffffffffu, ts[g], 1);
            ts[g] += __shfl_xor_sync(0xffffffffu, ts[g], 2);
            sum[g] = sum[g]*sc[g] + ts[g];
        }
        #pragma unroll
        for (int mf = 0; mf < 2; mf++)
            #pragma unroll
            for (int dn = 0; dn < 4; dn++) {
                o[mf][dn][0] *= sc[mf*2];     o[mf][dn][1] *= sc[mf*2];
                o[mf][dn][2] *= sc[mf*2 + 1]; o[mf][dn][3] *= sc[mf*2 + 1];
            }

        // ---- P -> shared (warp-local) ----
        #pragma unroll
        for (int mf = 0; mf < 2; mf++)
            #pragma unroll
            for (int jn = 0; jn < 8; jn++) {
                *(float2*)&Psh[pr + mf*16    ][jn*8 + 2*qq] =
                    make_float2(s[mf][jn][0], s[mf][jn][1]);
                *(float2*)&Psh[pr + mf*16 + 8][jn*8 + 2*qq] =
                    make_float2(s[mf][jn][2], s[mf][jn][3]);
            }
        __syncwarp();

        // ---- dead s regs: prefetch next tile's mask ----
        if (tix + 1 < LL/64) {
            const int j0n = j0 + 64;
            #pragma unroll
            for (int mf = 0; mf < 2; mf++)
                #pragma unroll
                for (int jn = 0; jn < 8; jn++) {
                    float2 a = __ldg((const float2*)&mrow[mf*2    ][j0n + jn*8 + 2*qq]);
                    float2 b = __ldg((const float2*)&mrow[mf*2 + 1][j0n + jn*8 + 2*qq]);
                    s[mf][jn][0] = a.x; s[mf][jn][1] = a.y;
                    s[mf][jn][2] = b.x; s[mf][jn][3] = b.y;
                }
        }

        // ---- O += P V : V b-frags shared across both m-frags ----
        #pragma unroll
        for (int kk = 0; kk < 8; kk++) {
            unsigned a[2][4];
            #pragma unroll
            for (int mf = 0; mf < 2; mf++) {
                a[mf][0] = __float_as_uint(Psh[pr + mf*16    ][kk*8 + qq    ]);
                a[mf][1] = __float_as_uint(Psh[pr + mf*16 + 8][kk*8 + qq    ]);
                a[mf][2] = __float_as_uint(Psh[pr + mf*16    ][kk*8 + qq + 4]);
                a[mf][3] = __float_as_uint(Psh[pr + mf*16 + 8][kk*8 + qq + 4]);
            }
            #pragma unroll
            for (int dn = 0; dn < 4; dn++) {
                unsigned b0 = __float_as_uint(Vsh[(kk*8 + qq    )*KSTR + dn*8 + qr]);
                unsigned b1 = __float_as_uint(Vsh[(kk*8 + qq + 4)*KSTR + dn*8 + qr]);
                mma_tf32(o[0][dn], a[0], b0, b1);
                mma_tf32(o[1][dn], a[1], b0, b1);
            }
        }
    }

    #pragma unroll
    for (int mf = 0; mf < 2; mf++) {
        float inv0 = 1.f / sum[mf*2], inv1 = 1.f / sum[mf*2 + 1];
        float* og0 = g_attn + ((size_t)(bi*LL + row0 + mf*16    ))*CC + n*HD;
        float* og1 = g_attn + ((size_t)(bi*LL + row0 + mf*16 + 8))*CC + n*HD;
        #pragma unroll
        for (int dn = 0; dn < 4; dn++) {
            *(float2*)&og0[dn*8 + 2*qq] =
                make_float2(o[mf][dn][0]*inv0, o[mf][dn][1]*inv0);
            *(float2*)&og1[dn*8 + 2*qq] =
                make_float2(o[mf][dn][2]*inv1, o[mf][dn][3]*inv1);
        }
    }
}

// ---------------- launch -------------------------------------------------------
extern "C" void kernel_launch(void* const* d_in, const int* in_sizes, int n_in,
                              void* d_out, int out_size)
{
    const float* x    = (const float*)d_in[0];
    const float* sinv = (const float*)d_in[1];
    const float* cosv = (const float*)d_in[2];
    const float* mask = (const float*)d_in[3];
    const float* wq   = (const float*)d_in[4];
    const float* bq   = (const float*)d_in[5];
    const float* wk   = (const float*)d_in[6];
    const float* bk   = (const float*)d_in[7];
    const float* wv   = (const float*)d_in[8];
    const float* bv   = (const float*)d_in[9];
    const float* wdw  = (const float*)d_in[10];
    const float* bdw  = (const float*)d_in[11];
    const float* wo   = (const float*)d_in[12];
    const float* bo   = (const float*)d_in[13];
    float* out = (float*)d_out;

    cudaFuncSetAttribute(attn_mma, cudaFuncAttributeMaxDynamicSharedMemorySize,
                         ATTN_SMEM);

    qkv_mma<<<dim3(CC/128, MTOT/32, 3), 256>>>(x, wq, bq, wk, bk, wv, bv,
                                               sinv, cosv);

    lepe_tiled<<<dim3(36, 4, BB), 256>>>(wdw, bdw);

    attn_mma<<<dim3(BB, LL/128, NHEAD), 128, ATTN_SMEM>>>(mask);

    out_mma<<<dim3(CC/128, MTOT/32), 256>>>(wo, bo, out);
}